// round 5
// baseline (speedup 1.0000x reference)
#include <cuda_runtime.h>

// Problem constants
#define KK 4
#define MM 32
#define DD 2048
#define TT 128
#define TTILE 16          // t-columns per CTA tile (64B of each 128B line)
#define NTHREADS 1024
#define NTILES (KK * MM * (TT / TTILE))   // 1024
#define NCTA 148

typedef unsigned long long u64;

// smem (u64 units)
#define PST 32
#define XS  1025                    // odd -> conflict-free .64 exchanges
#define XCH_U64 (TTILE * XS)        // 16400
#define SPAR 1024
#define SMEM_BYTES ((XCH_U64 + 4 * SPAR) * 8)

#define HNORM 0.022097086912079608f   // 1/sqrt(2048), folded per diagonal

// ---- packed f32x2 helpers (sm_103a) ----
__device__ __forceinline__ u64 addx2(u64 a, u64 b) {
    u64 r; asm("add.rn.f32x2 %0,%1,%2;" : "=l"(r) : "l"(a), "l"(b)); return r;
}
__device__ __forceinline__ u64 subx2(u64 a, u64 b) {
    u64 r; asm("sub.rn.f32x2 %0,%1,%2;" : "=l"(r) : "l"(a), "l"(b)); return r;
}
__device__ __forceinline__ u64 mulx2(u64 a, u64 b) {
    u64 r; asm("mul.rn.f32x2 %0,%1,%2;" : "=l"(r) : "l"(a), "l"(b)); return r;
}
__device__ __forceinline__ u64 pk(float lo, float hi) {
    u64 r; asm("mov.b64 %0,{%1,%2};" : "=l"(r) : "f"(lo), "f"(hi)); return r;
}
__device__ __forceinline__ void upk(float& lo, float& hi, u64 v) {
    asm("mov.b64 {%0,%1},%2;" : "=f"(lo), "=f"(hi) : "l"(v));
}

#define BFLY(A, B) { u64 _a = (A), _b = (B); (A) = addx2(_a, _b); (B) = subx2(_a, _b); }

// local stages over 16-reg array (index-bit strides 1,2,4,8 of the owned set)
#define LOCAL4(y) \
    { _Pragma("unroll") for (int s = 1; s < 16; s <<= 1) { \
        _Pragma("unroll") for (int j = 0; j < 16; ++j) \
            if ((j & s) == 0) BFLY(y[j], y[j | s]); } }

// cross-thread stage (bit held by q = lane bit 4); sign-mask trick keeps it 1 add
#define CROSS(y) \
    { _Pragma("unroll") for (int i = 0; i < 16; ++i) { \
        u64 _o = __shfl_xor_sync(0xffffffffu, y[i], 16); \
        y[i] = addx2(_o, y[i] ^ QM); } }

// intra-register stage (packed pair = d, d+32)
#define INTRA(y) \
    { _Pragma("unroll") for (int i = 0; i < 16; ++i) { \
        float _lo, _hi; upk(_lo, _hi, y[i]); \
        y[i] = pk(_lo + _hi, _lo - _hi); } }

__global__ __launch_bounds__(NTHREADS, 1)
void spinner_main_kernel(const float* __restrict__ z,
                         const float* __restrict__ d1,
                         const float* __restrict__ d2,
                         const float* __restrict__ d3,
                         const float* __restrict__ bia,
                         const float* __restrict__ sldj_in,
                         float* __restrict__ out)
{
    extern __shared__ u64 smem8[];
    u64* xch  = smem8;
    u64* spar = smem8 + XCH_U64;   // [a][c*32+p] = packed (v[c*64+p], v[c*64+p+32])

    const int tid = threadIdx.x;
    const int bid = blockIdx.x;

    // ---- stage params once per persistent CTA ----
    {
        int c = tid >> 5, p = tid & 31;
        int d = c * 64 + p;
        spar[0 * SPAR + tid] = pk(d1[d] * HNORM, d1[d + 32] * HNORM);
        spar[1 * SPAR + tid] = pk(d2[d] * HNORM, d2[d + 32] * HNORM);
        spar[2 * SPAR + tid] = pk(d3[d] * HNORM, d3[d + 32] * HNORM);
        spar[3 * SPAR + tid] = pk(bia[d], bia[d + 32]);
    }
    __syncthreads();

    // ---- sldj on the lightest CTA (147: 6 tiles), before its loop ----
    if (bid == NCTA - 1) {
        float* red = (float*)xch;   // scratch; reused at E1 (guarded by pre-E1 sync)
        float s = 0.f;
        #pragma unroll
        for (int r = 0; r < 2; ++r) {
            int i = tid + r * NTHREADS;
            s += logf(fabsf(d1[i])) + logf(fabsf(d2[i])) + logf(fabsf(d3[i]));
        }
        #pragma unroll
        for (int o = 16; o > 0; o >>= 1) s += __shfl_xor_sync(0xffffffffu, s, o);
        if ((tid & 31) == 0) red[tid >> 5] = s;
        __syncthreads();
        if (tid < 32) {
            float v = red[tid];
            #pragma unroll
            for (int o = 16; o > 0; o >>= 1) v += __shfl_xor_sync(0xffffffffu, v, o);
            if (tid == 0) red[40] = v;
        }
        __syncthreads();
        if (tid < KK * MM)
            out[(size_t)KK * MM * DD * TT + tid] = sldj_in[tid] + red[40];
    }

    const int t = tid & 15;          // t-column (lane bits 0-3)
    const int q = (tid >> 4) & 1;    // split bit (lane bit 4)
    const int u = tid >> 5;          // phase-1 chunk / phase-2 row (0..31)
    const u64 QM = q ? 0x8000000080000000ULL : 0ULL;
    u64* xc = xch + t * XS;

    // static balanced tile split: CTAs 0..135 get 7 tiles, 136..147 get 6
    const int extra = (bid < 136) ? bid : 136;
    const int start = bid * 6 + extra;
    const int cnt   = 6 + (bid < 136 ? 1 : 0);

    for (int it = 0; it < cnt; ++it) {
        const int tile = start + it;
        const int km = tile >> 3;
        const int t0 = (tile & 7) * TTILE;
        const float* zin  = z   + (size_t)km * (DD * TT) + (t0 + t);
        float*       zout = out + (size_t)km * (DD * TT) + (t0 + t);

        u64 y[16];

        // ---- load + d1 scale (phase-1: d = u*64 + 2i + q, pair packs +32) ----
        #pragma unroll
        for (int i = 0; i < 16; ++i) {
            int dlo = u * 64 + 2 * i + q;
            y[i] = mulx2(pk(zin[(size_t)dlo * TT], zin[(size_t)(dlo + 32) * TT]),
                         spar[0 * SPAR + u * 32 + 2 * i + q]);
        }

        // ---- FWHT #1: H64 over p ----
        CROSS(y); LOCAL4(y); INTRA(y);

        __syncthreads();   // WAR vs previous tile's E3-reads (and sldj scratch)

        // E1: phase-1 -> phase-2
        #pragma unroll
        for (int i = 0; i < 16; ++i) xc[(2 * i + q) * PST + u] = y[i];
        __syncthreads();
        #pragma unroll
        for (int j = 0; j < 16; ++j) y[j] = xc[u * PST + 2 * j + q];

        // ---- FWHT #1: H32 over c ----
        CROSS(y); LOCAL4(y);

        // ---- d2 scale ----
        #pragma unroll
        for (int j = 0; j < 16; ++j)
            y[j] = mulx2(y[j], spar[1 * SPAR + (2 * j + q) * 32 + u]);

        // ---- FWHT #2: H32 over c ----
        LOCAL4(y); CROSS(y);

        // E2: phase-2 -> phase-1 (writes exactly this thread's E1-read slots: no pre-sync)
        #pragma unroll
        for (int j = 0; j < 16; ++j) xc[u * PST + 2 * j + q] = y[j];
        __syncthreads();
        #pragma unroll
        for (int i = 0; i < 16; ++i) y[i] = xc[(2 * i + q) * PST + u];

        // ---- FWHT #2: H64 over p ----
        INTRA(y); LOCAL4(y); CROSS(y);

        // ---- d3 scale ----
        #pragma unroll
        for (int i = 0; i < 16; ++i)
            y[i] = mulx2(y[i], spar[2 * SPAR + u * 32 + 2 * i + q]);

        // ---- FWHT #3: H64 over p ----
        CROSS(y); LOCAL4(y); INTRA(y);

        // E3: phase-1 -> phase-2 (writes this thread's E2-read slots: no pre-sync)
        #pragma unroll
        for (int i = 0; i < 16; ++i) xc[(2 * i + q) * PST + u] = y[i];
        __syncthreads();
        #pragma unroll
        for (int j = 0; j < 16; ++j) y[j] = xc[u * PST + 2 * j + q];

        // ---- FWHT #3: H32 over c ----
        CROSS(y); LOCAL4(y);

        // ---- bias + store ----
        #pragma unroll
        for (int j = 0; j < 16; ++j) {
            u64 r = addx2(y[j], spar[3 * SPAR + (2 * j + q) * 32 + u]);
            float lo, hi; upk(lo, hi, r);
            int dlo = (2 * j + q) * 64 + u;
            zout[(size_t)dlo * TT]        = lo;
            zout[(size_t)(dlo + 32) * TT] = hi;
        }
    }
}

extern "C" void kernel_launch(void* const* d_in, const int* in_sizes, int n_in,
                              void* d_out, int out_size)
{
    (void)in_sizes; (void)n_in; (void)out_size;
    const float* z    = (const float*)d_in[0];
    const float* d1   = (const float*)d_in[1];
    const float* d2   = (const float*)d_in[2];
    const float* d3   = (const float*)d_in[3];
    const float* bia  = (const float*)d_in[4];
    const float* sldj = (const float*)d_in[5];
    float* out = (float*)d_out;

    cudaFuncSetAttribute(spinner_main_kernel,
                         cudaFuncAttributeMaxDynamicSharedMemorySize, SMEM_BYTES);

    spinner_main_kernel<<<NCTA, NTHREADS, SMEM_BYTES>>>(
        z, d1, d2, d3, bia, sldj, out);
}

// round 6
// speedup vs baseline: 1.0164x; 1.0164x over previous
#include <cuda_runtime.h>

// Problem constants
#define KK 4
#define MM 32
#define DD 2048
#define TT 128
#define TTILE 8           // t-columns per CTA
#define NTH 512
#define NTILES 2048       // KK*MM * (TT/TTILE)

typedef unsigned long long u64;

// smem (u64): xch 8192 (64KB) + spar 4*1024 (32KB) = 96KB
#define XCH_U64 8192
#define SPAR 1024
#define SMEM_BYTES ((XCH_U64 + 4 * SPAR) * 8)

#define HNORM 0.022097086912079608f   // 1/sqrt(2048), folded per diagonal

// ---- packed f32x2 helpers (sm_103a) ----
__device__ __forceinline__ u64 addx2(u64 a, u64 b) {
    u64 r; asm("add.rn.f32x2 %0,%1,%2;" : "=l"(r) : "l"(a), "l"(b)); return r;
}
__device__ __forceinline__ u64 subx2(u64 a, u64 b) {
    u64 r; asm("sub.rn.f32x2 %0,%1,%2;" : "=l"(r) : "l"(a), "l"(b)); return r;
}
__device__ __forceinline__ u64 mulx2(u64 a, u64 b) {
    u64 r; asm("mul.rn.f32x2 %0,%1,%2;" : "=l"(r) : "l"(a), "l"(b)); return r;
}
__device__ __forceinline__ u64 pk(float lo, float hi) {
    u64 r; asm("mov.b64 %0,{%1,%2};" : "=l"(r) : "f"(lo), "f"(hi)); return r;
}
__device__ __forceinline__ void upk(float& lo, float& hi, u64 v) {
    asm("mov.b64 {%0,%1},%2;" : "=f"(lo), "=f"(hi) : "l"(v));
}

#define BFLY(A, B) { u64 _a = (A), _b = (B); (A) = addx2(_a, _b); (B) = subx2(_a, _b); }

// 4 local stages over 16-reg array (owned-bit strides 1,2,4,8)
#define LOCAL4(y) \
    { _Pragma("unroll") for (int s = 1; s < 16; s <<= 1) { \
        _Pragma("unroll") for (int j = 0; j < 16; ++j) \
            if ((j & s) == 0) BFLY(y[j], y[j | s]); } }

// cross-lane stage over q (lane bit 4)
#define CROSS(y) \
    { _Pragma("unroll") for (int i = 0; i < 16; ++i) { \
        u64 _o = __shfl_xor_sync(0xffffffffu, y[i], 16); \
        y[i] = addx2(_o, y[i] ^ QM); } }

// intra-register stage (packed pair = d, d+32)
#define INTRA(y) \
    { _Pragma("unroll") for (int i = 0; i < 16; ++i) { \
        float _lo, _hi; upk(_lo, _hi, y[i]); \
        y[i] = pk(_lo + _hi, _lo - _hi); } }

__global__ __launch_bounds__(NTH, 2)
void spinner_main_kernel(const float* __restrict__ z,
                         const float* __restrict__ d1,
                         const float* __restrict__ d2,
                         const float* __restrict__ d3,
                         const float* __restrict__ bia,
                         const float* __restrict__ sldj_in,
                         float* __restrict__ out)
{
    extern __shared__ __align__(16) u64 smem8[];
    const int tid = threadIdx.x;
    const int bid = blockIdx.x;

    // ---- extra CTA: sldj ----
    if (bid == NTILES) {
        float* red = (float*)smem8;
        float s = 0.f;
        #pragma unroll
        for (int r = 0; r < 4; ++r) {
            int i = tid + r * NTH;
            s += logf(fabsf(d1[i])) + logf(fabsf(d2[i])) + logf(fabsf(d3[i]));
        }
        #pragma unroll
        for (int o = 16; o > 0; o >>= 1) s += __shfl_xor_sync(0xffffffffu, s, o);
        if ((tid & 31) == 0) red[tid >> 5] = s;
        __syncthreads();
        if (tid < 32) {
            float v = (tid < NTH / 32) ? red[tid] : 0.f;
            #pragma unroll
            for (int o = 16; o > 0; o >>= 1) v += __shfl_xor_sync(0xffffffffu, v, o);
            if (tid == 0) red[40] = v;
        }
        __syncthreads();
        if (tid < KK * MM)
            out[(size_t)KK * MM * DD * TT + tid] = sldj_in[tid] + red[40];
        return;
    }

    u64* xch  = smem8;
    u64* spar = smem8 + XCH_U64;   // [a][c*32+p^] = packed (v[c*64+p], v[c*64+p+32])

    // stage params (2 entries per thread)
    #pragma unroll
    for (int r = 0; r < 2; ++r) {
        int e = tid + r * NTH;
        int d = (e >> 5) * 64 + (e & 31);
        spar[0 * SPAR + e] = pk(d1[d] * HNORM, d1[d + 32] * HNORM);
        spar[1 * SPAR + e] = pk(d2[d] * HNORM, d2[d + 32] * HNORM);
        spar[2 * SPAR + e] = pk(d3[d] * HNORM, d3[d + 32] * HNORM);
        spar[3 * SPAR + e] = pk(bia[d], bia[d + 32]);
    }
    __syncthreads();

    // lane decode: bits0-2 = t, bit3 = u-lsb, bit4 = q  (bank-phase layout)
    const int t  = tid & 7;
    const int ub = (tid >> 3) & 1;
    const int q  = (tid >> 4) & 1;
    const int u  = ((tid >> 5) << 1) | ub;      // 0..31
    const u64 QM = q ? 0x8000000080000000ULL : 0ULL;

    // exchange-slot bases: S(p^,c,t) = (p^>>1)*512 + (c>>1)*32 + (p^&1)*16 + 2t + (c&1)
    const int base_w0 = (u >> 1) * 32 + 2 * t + ub;           // rows 2i(+q), col u
    const int base_r1 = (u >> 1) * 512 + ub * 16 + 2 * t;     // row u, col-pairs

    const int km = bid >> 4;
    const int t0 = (bid & 15) * TTILE;
    const float* zin  = z   + (size_t)km * (DD * TT) + (t0 + t);
    float*       zout = out + (size_t)km * (DD * TT) + (t0 + t);

    u64 y[16];

    // ---- load + d1 scale (phase-1: c=u, p = 2i+q, packed with +32) ----
    {
        const float* zrow = zin + (size_t)(u * 64 + q) * TT;
        #pragma unroll
        for (int i = 0; i < 16; ++i)
            y[i] = mulx2(pk(zrow[(size_t)i * 2 * TT], zrow[(size_t)(i * 2 + 32) * TT]),
                         spar[0 * SPAR + u * 32 + q + 2 * i]);
    }

    // ---- FWHT #1: H64 over p ----
    CROSS(y); LOCAL4(y); INTRA(y);

    // E1-write: slot (p^=2i+q, c=u)
    #pragma unroll
    for (int i = 0; i < 16; ++i) xch[base_w0 + q * 16 + i * 512] = y[i];
    __syncthreads();
    // E1-read (.128 pair, folded c-stride-1 butterfly): row u, cols (2j,2j+1)
    #pragma unroll
    for (int j = 0; j < 16; ++j) {
        ulonglong2 v = *(const ulonglong2*)(xch + base_r1 + j * 32);
        y[j] = addx2(v.x, v.y ^ QM);          // keeps c = 2j+q
    }

    // ---- FWHT #1: H32c remaining stages ----
    LOCAL4(y);

    // ---- d2 scale ----
    #pragma unroll
    for (int j = 0; j < 16; ++j)
        y[j] = mulx2(y[j], spar[1 * SPAR + q * 32 + u + j * 64]);

    // ---- FWHT #2: H32 over c ----
    LOCAL4(y); CROSS(y);

    // E2-write: slot (p^=u, c=2j+q)  [writer's own warp read these in E1: safe]
    #pragma unroll
    for (int j = 0; j < 16; ++j) xch[base_r1 + j * 32 + q] = y[j];
    __syncthreads();
    // E2-read (paired rows, folded p-stride-1): rows (2i, 2i+1), col u
    #pragma unroll
    for (int i = 0; i < 16; ++i) {
        u64 a = xch[base_w0 + i * 512];
        u64 b = xch[base_w0 + i * 512 + 16];
        y[i] = addx2(a, b ^ QM);              // keeps p = 2i+q
    }

    // ---- FWHT #2: H64p remaining stages ----
    LOCAL4(y); INTRA(y);

    // ---- d3 scale ----
    #pragma unroll
    for (int i = 0; i < 16; ++i)
        y[i] = mulx2(y[i], spar[2 * SPAR + u * 32 + q + 2 * i]);

    // ---- FWHT #3: H64 over p ----
    CROSS(y); LOCAL4(y); INTRA(y);

    // E3-write: slot (p^=2i+q, c=u)  [own warp read these in E2: safe]
    #pragma unroll
    for (int i = 0; i < 16; ++i) xch[base_w0 + q * 16 + i * 512] = y[i];
    __syncthreads();
    // E3-read (.128 pair, folded c-stride-1)
    #pragma unroll
    for (int j = 0; j < 16; ++j) {
        ulonglong2 v = *(const ulonglong2*)(xch + base_r1 + j * 32);
        y[j] = addx2(v.x, v.y ^ QM);
    }

    // ---- FWHT #3: H32c remaining stages ----
    LOCAL4(y);

    // ---- bias + store (c = 2j+q, rows u / u+32) ----
    {
        float* zrow = zout + (size_t)(q * 64 + u) * TT;
        #pragma unroll
        for (int j = 0; j < 16; ++j) {
            u64 r = addx2(y[j], spar[3 * SPAR + q * 32 + u + j * 64]);
            float lo, hi; upk(lo, hi, r);
            zrow[(size_t)j * 128 * TT]        = lo;
            zrow[(size_t)(j * 128 + 32) * TT] = hi;
        }
    }
}

extern "C" void kernel_launch(void* const* d_in, const int* in_sizes, int n_in,
                              void* d_out, int out_size)
{
    (void)in_sizes; (void)n_in; (void)out_size;
    const float* z    = (const float*)d_in[0];
    const float* d1   = (const float*)d_in[1];
    const float* d2   = (const float*)d_in[2];
    const float* d3   = (const float*)d_in[3];
    const float* bia  = (const float*)d_in[4];
    const float* sldj = (const float*)d_in[5];
    float* out = (float*)d_out;

    cudaFuncSetAttribute(spinner_main_kernel,
                         cudaFuncAttributeMaxDynamicSharedMemorySize, SMEM_BYTES);

    spinner_main_kernel<<<NTILES + 1, NTH, SMEM_BYTES>>>(
        z, d1, d2, d3, bia, sldj, out);
}